// round 1
// baseline (speedup 1.0000x reference)
#include <cuda_runtime.h>

// Problem constants: B=32, C=1, H=512, W=512
// 2x2 blocks: 32*256*256 = 2,097,152 blocks
// float4 quads covering 2 blocks each: 32*256*128 = 1,048,576 quad-columns
#define N_QUADS  (32 * 256 * 128)
#define N_BLOCKS_TOTAL 2097152.0f

__global__ void zero_out_kernel(float* out) {
    if (threadIdx.x < 2) out[threadIdx.x] = 0.0f;
}

__global__ __launch_bounds__(256) void haar_loss_kernel(
    const float4* __restrict__ in,
    const float4* __restrict__ tgt,
    float* __restrict__ out)
{
    float lo = 0.0f, hi = 0.0f;

    const int stride = gridDim.x * blockDim.x;
    for (int q = blockIdx.x * blockDim.x + threadIdx.x; q < N_QUADS; q += stride) {
        // q -> (row-pair grp, quad-column c4). Each image is 512 rows of 512
        // floats; a row-pair = 1024 floats = 256 float4. Images are contiguous
        // and 512 is even, so grp indexes row-pairs globally across images.
        const int grp = q >> 7;        // / 128 quads per row
        const int c4  = q & 127;
        const int base0 = grp * 256 + c4;   // row 2r  (float4 units)
        const int base1 = base0 + 128;      // row 2r+1

        const float4 i0 = in[base0];
        const float4 i1 = in[base1];
        const float4 t0 = tgt[base0];
        const float4 t1 = tgt[base1];

        // diffs: row0 holds (a0, b0, a1, b1), row1 holds (c0, d0, c1, d1)
        const float da0 = i0.x - t0.x, db0 = i0.y - t0.y;
        const float da1 = i0.z - t0.z, db1 = i0.w - t0.w;
        const float dc0 = i1.x - t1.x, dd0 = i1.y - t1.y;
        const float dc1 = i1.z - t1.z, dd1 = i1.w - t1.w;

        // Haar butterfly on the diff (factor 0.5 folded into final scale):
        //   ll = p + q, lh = q - p, hl = -(u + v), hh = u - v
        // with p=a+b, q=c+d, u=a-b, v=c-d
        {
            const float p = da0 + db0, qq = dc0 + dd0;
            const float u = da0 - db0, v  = dc0 - dd0;
            lo += fabsf(p + qq);
            hi += fabsf(qq - p) + fabsf(u + v) + fabsf(u - v);
        }
        {
            const float p = da1 + db1, qq = dc1 + dd1;
            const float u = da1 - db1, v  = dc1 - dd1;
            lo += fabsf(p + qq);
            hi += fabsf(qq - p) + fabsf(u + v) + fabsf(u - v);
        }
    }

    // warp reduction
    #pragma unroll
    for (int o = 16; o > 0; o >>= 1) {
        lo += __shfl_xor_sync(0xffffffffu, lo, o);
        hi += __shfl_xor_sync(0xffffffffu, hi, o);
    }

    __shared__ float slo[8], shi[8];
    const int warp = threadIdx.x >> 5;
    const int lane = threadIdx.x & 31;
    if (lane == 0) { slo[warp] = lo; shi[warp] = hi; }
    __syncthreads();

    if (threadIdx.x < 32) {
        lo = (lane < 8) ? slo[lane] : 0.0f;
        hi = (lane < 8) ? shi[lane] : 0.0f;
        #pragma unroll
        for (int o = 4; o > 0; o >>= 1) {
            lo += __shfl_xor_sync(0xffffffffu, lo, o);
            hi += __shfl_xor_sync(0xffffffffu, hi, o);
        }
        if (lane == 0) {
            // mean over all blocks, with the 0.5 Haar factor; /3 for high band
            const float sL = 0.5f / N_BLOCKS_TOTAL;
            const float sH = 0.5f / (3.0f * N_BLOCKS_TOTAL);
            atomicAdd(&out[0], lo * sL);
            atomicAdd(&out[1], hi * sH);
        }
    }
}

extern "C" void kernel_launch(void* const* d_in, const int* in_sizes, int n_in,
                              void* d_out, int out_size) {
    const float4* in  = (const float4*)d_in[0];
    const float4* tgt = (const float4*)d_in[1];
    float* out = (float*)d_out;

    zero_out_kernel<<<1, 32>>>(out);

    // 2048 CTAs x 256 threads = 524,288 threads; 2 grid-stride iters each.
    haar_loss_kernel<<<2048, 256>>>(in, tgt, out);
}

// round 2
// speedup vs baseline: 1.3761x; 1.3761x over previous
#include <cuda_runtime.h>

// Problem constants: B=32, C=1, H=512, W=512 (fp32), two inputs.
// 2x2 Haar blocks: 32*256*256 = 2,097,152. One float4 "quad-pair" (a float4
// from row 2r and the float4 below it in row 2r+1, from both tensors) covers
// 2 Haar blocks. Total quad-pairs N_QUADS = 32*256*128 = 1,048,576.
#define N_BLOCKS_TOTAL 2097152.0f

#define CTAS    512
#define THREADS 256
#define PAIRS   8
#define STRIDE  (CTAS * THREADS)   // 131072; CTAS*THREADS*PAIRS == N_QUADS exactly

__global__ void zero_out_kernel(float* out) {
    if (threadIdx.x < 2) out[threadIdx.x] = 0.0f;
}

// quad index p -> float4 offsets of the two stacked rows.
// grp = p>>7 (row-pair id), c4 = p&127; base0 = grp*256 + c4 = 2*p - c4.
__device__ __forceinline__ void load_pair(
    const float4* __restrict__ in, const float4* __restrict__ tgt, int p,
    float4& i0, float4& i1, float4& t0, float4& t1)
{
    const int c4    = p & 127;
    const int base0 = 2 * p - c4;
    const int base1 = base0 + 128;
    i0 = in[base0];
    i1 = in[base1];
    t0 = tgt[base0];
    t1 = tgt[base1];
}

__device__ __forceinline__ void haar_accum(
    const float4& i0, const float4& i1, const float4& t0, const float4& t1,
    float& lo, float& hi)
{
    // diffs: row0 = (a0,b0,a1,b1), row1 = (c0,d0,c1,d1)
    const float da0 = i0.x - t0.x, db0 = i0.y - t0.y;
    const float da1 = i0.z - t0.z, db1 = i0.w - t0.w;
    const float dc0 = i1.x - t1.x, dd0 = i1.y - t1.y;
    const float dc1 = i1.z - t1.z, dd1 = i1.w - t1.w;

    // Haar butterfly on the diff (0.5 factor folded into final scale):
    // ll = p+q, lh = q-p, hl = -(u+v), hh = u-v  with p=a+b,q=c+d,u=a-b,v=c-d
    {
        const float p = da0 + db0, qq = dc0 + dd0;
        const float u = da0 - db0, v  = dc0 - dd0;
        lo += fabsf(p + qq);
        hi += fabsf(qq - p) + fabsf(u + v) + fabsf(u - v);
    }
    {
        const float p = da1 + db1, qq = dc1 + dd1;
        const float u = da1 - db1, v  = dc1 - dd1;
        lo += fabsf(p + qq);
        hi += fabsf(qq - p) + fabsf(u + v) + fabsf(u - v);
    }
}

__global__ __launch_bounds__(THREADS, 4) void haar_loss_kernel(
    const float4* __restrict__ in,
    const float4* __restrict__ tgt,
    float* __restrict__ out)
{
    const int q0 = blockIdx.x * THREADS + threadIdx.x;

    float lo = 0.0f, hi = 0.0f;

    // 2-deep software pipeline over PAIRS fully-unrolled iterations:
    // while computing batch j, batch j+1's 4 loads are in flight.
    float4 ci0, ci1, ct0, ct1;
    load_pair(in, tgt, q0, ci0, ci1, ct0, ct1);

    #pragma unroll
    for (int j = 0; j < PAIRS; j++) {
        float4 ni0, ni1, nt0, nt1;
        if (j + 1 < PAIRS) {
            load_pair(in, tgt, q0 + (j + 1) * STRIDE, ni0, ni1, nt0, nt1);
        }
        haar_accum(ci0, ci1, ct0, ct1, lo, hi);
        if (j + 1 < PAIRS) {
            ci0 = ni0; ci1 = ni1; ct0 = nt0; ct1 = nt1;
        }
    }

    // warp reduction
    #pragma unroll
    for (int o = 16; o > 0; o >>= 1) {
        lo += __shfl_xor_sync(0xffffffffu, lo, o);
        hi += __shfl_xor_sync(0xffffffffu, hi, o);
    }

    __shared__ float slo[8], shi[8];
    const int warp = threadIdx.x >> 5;
    const int lane = threadIdx.x & 31;
    if (lane == 0) { slo[warp] = lo; shi[warp] = hi; }
    __syncthreads();

    if (threadIdx.x < 32) {
        lo = (lane < 8) ? slo[lane] : 0.0f;
        hi = (lane < 8) ? shi[lane] : 0.0f;
        #pragma unroll
        for (int o = 4; o > 0; o >>= 1) {
            lo += __shfl_xor_sync(0xffffffffu, lo, o);
            hi += __shfl_xor_sync(0xffffffffu, hi, o);
        }
        if (lane == 0) {
            const float sL = 0.5f / N_BLOCKS_TOTAL;
            const float sH = 0.5f / (3.0f * N_BLOCKS_TOTAL);
            atomicAdd(&out[0], lo * sL);
            atomicAdd(&out[1], hi * sH);
        }
    }
}

extern "C" void kernel_launch(void* const* d_in, const int* in_sizes, int n_in,
                              void* d_out, int out_size) {
    const float4* in  = (const float4*)d_in[0];
    const float4* tgt = (const float4*)d_in[1];
    float* out = (float*)d_out;

    zero_out_kernel<<<1, 32>>>(out);
    haar_loss_kernel<<<CTAS, THREADS>>>(in, tgt, out);
}